// round 14
// baseline (speedup 1.0000x reference)
#include <cuda_runtime.h>
#include <cstdint>

#define WIN    100
#define H      64
#define AA     64
#define KK     8
#define NAPP   4
#define DT     0.1f
#define LN_EPS 1e-5f
#define TPB    128
#define SPC    64
#define BMAX   32768

#define SWGT_FLOATS (WIN * AA + AA * AA)        // 10496 floats
#define SLAB_U64_PER_WARP (H * 4 * 4)           // 64ch x 4slots x 4samples(dup'd) = 1024 u64 = 8KB
#define DYN_BYTES (SWGT_FLOATS * 4 + 4 * SLAB_U64_PER_WARP * 8)   // 41984 + 32768 = 74,752B

// gmem scratch
__device__ uint64_t g_ytd[(size_t)WIN * BMAX];   // y transposed AND duplicated {y,y}
__device__ float g_wet[KK * WIN * AA];           // We transposed [k][t][a]
__device__ float g_wrt[KK * AA * AA];            // Wr transposed [k][i][a]
__device__ float g_wx0t[AA * AA];                // Wx0 transposed [i][a]

__device__ __forceinline__ float softplus_f(float v) {
    return (v > 20.f) ? v : log1pf(expf(v));
}
__device__ __forceinline__ float tanh_fast(float x) {
    float r; asm("tanh.approx.f32 %0, %1;" : "=f"(r) : "f"(x)); return r;
}
__device__ __forceinline__ uint64_t dup2(float a) {
    uint64_t r; asm("mov.b64 %0, {%1, %1};" : "=l"(r) : "f"(a)); return r;
}
__device__ __forceinline__ uint64_t pk2(float x, float y) {
    uint64_t r; asm("mov.b64 %0, {%1, %2};" : "=l"(r) : "f"(x), "f"(y)); return r;
}
__device__ __forceinline__ void upk2(float& x, float& y, uint64_t d) {
    asm("mov.b64 {%0, %1}, %2;" : "=f"(x), "=f"(y) : "l"(d));
}
__device__ __forceinline__ void ffma2(uint64_t& d, uint64_t a, uint64_t b) {
    asm("fma.rn.f32x2 %0, %1, %2, %0;" : "+l"(d) : "l"(a), "l"(b));
}
__device__ __forceinline__ void add2(uint64_t& d, uint64_t a) {
    asm("add.rn.f32x2 %0, %0, %1;" : "+l"(d) : "l"(a));
}

// ---------------- merged prep kernel ----------------
__global__ void prep_all_kernel(const float* __restrict__ y,
                                const float* __restrict__ We,
                                const float* __restrict__ Wr,
                                const float* __restrict__ Wx0,
                                int B, int nBB, int nYBlocks) {
    __shared__ float tile[32][33];
    const int tid = threadIdx.x;
    if ((int)blockIdx.x < nYBlocks) {
        const int bb = (blockIdx.x % nBB) * 32;
        const int tt = (blockIdx.x / nBB) * 32;
        const int tx = tid & 31, ty = tid >> 5;
        for (int r = ty; r < 32; r += 8) {
            const int b = bb + r, t = tt + tx;
            tile[r][tx] = (b < B && t < WIN) ? y[(long)b * WIN + t] : 0.f;
        }
        __syncthreads();
        for (int r = ty; r < 32; r += 8) {
            const int t = tt + r, b = bb + tx;
            if (t < WIN && b < B) g_ytd[(size_t)t * BMAX + b] = dup2(tile[tx][r]);
        }
        return;
    }
    const int idx = (blockIdx.x - nYBlocks) * blockDim.x + tid;
    if (idx < KK * WIN * AA) {
        const int k = idx / (WIN * AA);
        const int rem = idx - k * WIN * AA;
        const int t = rem >> 6, a = rem & 63;
        g_wet[idx] = We[k * AA * WIN + a * WIN + t];
        return;
    }
    const int i2 = idx - KK * WIN * AA;
    if (i2 >= 0 && i2 < KK * AA * AA) {
        const int k = i2 >> 12;
        const int rem = i2 & 4095;
        const int i = rem >> 6, a = rem & 63;
        g_wrt[i2] = Wr[k * AA * AA + a * AA + i];
        return;
    }
    const int i3 = i2 - KK * AA * AA;
    if (i3 >= 0 && i3 < AA * AA) {
        const int i = i3 >> 6, a = i3 & 63;
        g_wx0t[i3] = Wx0[a * AA + i];
    }
}

// ---------------- main kernel ----------------
__global__ __launch_bounds__(TPB, 3)
void pinn_main_kernel(
    const float* __restrict__ w_in,
    const float* __restrict__ b_in,
    const float* __restrict__ tau_param,
    const float* __restrict__ W_rec,
    const float* __restrict__ ln_w,
    const float* __restrict__ ln_b,
    const float* __restrict__ bx0,
    const float* __restrict__ be,
    const float* __restrict__ thr,
    const float* __restrict__ head_W,
    const float* __restrict__ head_b,
    float* __restrict__ out_power,
    float* __restrict__ out_x,
    int B)
{
    extern __shared__ __align__(16) float smem[];
    float* sWgt = smem;                                   // weights region
    ulonglong2* HsU = reinterpret_cast<ulonglong2*>(smem + SWGT_FLOATS);

    __shared__ float s_vec[AA], s_lam[AA];                // only small per-k staging is static

    const int tid  = threadIdx.x;
    const int warp = tid >> 5, lane = tid & 31;
    const int cg   = lane & 7;
    const int sg   = lane >> 3;
    const int c0   = cg * 8;
    const int s0   = blockIdx.x * SPC + warp * 16 + sg * 4;
    const unsigned FULL = 0xffffffffu;

    ulonglong2* HsW = HsU + warp * (SLAB_U64_PER_WARP / 2);   // per-warp slab (ulonglong2 units)
    const int myslot = sg ^ (cg & 3);

    // ---- stage W_rec + zero slab ----
    for (int i = tid; i < H * H; i += TPB) sWgt[i] = W_rec[i];
    {
        const ulonglong2 z2 = make_ulonglong2(0ull, 0ull);
        #pragma unroll
        for (int cc = 0; cc < 8; cc++) {
            const int idx2 = ((c0 + cc) * 4 + myslot) * 2;
            HsW[idx2] = z2; HsW[idx2 + 1] = z2;
        }
    }
    __syncthreads();

    // ---- hoist per-channel constants straight from gmem (no smem staging) ----
    uint64_t win2p[4], bin2p[4];
    float2 lnw2[4], lnb2[4], dec2[4];
    #pragma unroll
    for (int cp = 0; cp < 4; cp++) {
        const int c = c0 + 2 * cp;
        const float2 w2 = __ldg(reinterpret_cast<const float2*>(w_in + c));
        const float2 b2 = __ldg(reinterpret_cast<const float2*>(b_in + c));
        win2p[cp] = pk2(w2.x, w2.y);
        bin2p[cp] = pk2(b2.x, b2.y);
        lnw2[cp] = __ldg(reinterpret_cast<const float2*>(ln_w + c));
        lnb2[cp] = __ldg(reinterpret_cast<const float2*>(ln_b + c));
        const float2 tp = __ldg(reinterpret_cast<const float2*>(tau_param + c));
        dec2[cp] = make_float2(DT / softplus_f(tp.x), DT / softplus_f(tp.y));
    }

    // ================= Phase 1: LNN recurrence =================
    float2 hv2[4][4];
    #pragma unroll
    for (int s = 0; s < 4; s++)
        #pragma unroll
        for (int cp = 0; cp < 4; cp++) hv2[s][cp] = make_float2(0.f, 0.f);

    {
        const ulonglong2* sWu = reinterpret_cast<const ulonglong2*>(sWgt);
        for (int t = 0; t < WIN; t++) {
            // y duplicated: 2 LDG.128, zero movs
            const ulonglong2* ydu = reinterpret_cast<const ulonglong2*>(g_ytd + (size_t)t * BMAX + s0);
            const ulonglong2 ya = __ldg(&ydu[0]);
            const ulonglong2 yb = __ldg(&ydu[1]);
            const uint64_t ys[4] = { ya.x, ya.y, yb.x, yb.y };
            uint64_t pre[4][4];
            #pragma unroll
            for (int s = 0; s < 4; s++)
                #pragma unroll
                for (int cp = 0; cp < 4; cp++) {
                    pre[s][cp] = bin2p[cp];
                    ffma2(pre[s][cp], ys[s], win2p[cp]);
                }
            // pre += h @ W_rec : per i = 2 slab LDS + 2 weight LDS + 16 FFMA2, NO movs
            for (int q = 0; q < 8; q++) {
                const int sl = sg ^ (q & 3);
                #pragma unroll
                for (int r = 0; r < 8; r++) {
                    const int i = q * 8 + r;
                    const ulonglong2 ha = HsW[(i * 4 + sl) * 2];       // {d(s0),d(s1)}
                    const ulonglong2 hb = HsW[(i * 4 + sl) * 2 + 1];   // {d(s2),d(s3)}
                    const ulonglong2 wa = sWu[i * 16 + cg * 2];
                    const ulonglong2 wb = sWu[i * 16 + cg * 2 + 1];
                    ffma2(pre[0][0], ha.x, wa.x); ffma2(pre[0][1], ha.x, wa.y);
                    ffma2(pre[0][2], ha.x, wb.x); ffma2(pre[0][3], ha.x, wb.y);
                    ffma2(pre[1][0], ha.y, wa.x); ffma2(pre[1][1], ha.y, wa.y);
                    ffma2(pre[1][2], ha.y, wb.x); ffma2(pre[1][3], ha.y, wb.y);
                    ffma2(pre[2][0], hb.x, wa.x); ffma2(pre[2][1], hb.x, wa.y);
                    ffma2(pre[2][2], hb.x, wb.x); ffma2(pre[2][3], hb.x, wb.y);
                    ffma2(pre[3][0], hb.y, wa.x); ffma2(pre[3][1], hb.y, wa.y);
                    ffma2(pre[3][2], hb.y, wb.x); ffma2(pre[3][3], hb.y, wb.y);
                }
            }
            // LN + tanh + Euler (packed stats + octet shfl)
            #pragma unroll
            for (int s = 0; s < 4; s++) {
                uint64_t smp = 0ull, sqp = 0ull;
                #pragma unroll
                for (int cp = 0; cp < 4; cp++) {
                    add2(smp, pre[s][cp]);
                    ffma2(sqp, pre[s][cp], pre[s][cp]);
                }
                float smx, smy, sqx, sqy;
                upk2(smx, smy, smp);
                upk2(sqx, sqy, sqp);
                float sm = smx + smy, sq = sqx + sqy;
                sm += __shfl_xor_sync(FULL, sm, 1, 32);
                sm += __shfl_xor_sync(FULL, sm, 2, 32);
                sm += __shfl_xor_sync(FULL, sm, 4, 32);
                sq += __shfl_xor_sync(FULL, sq, 1, 32);
                sq += __shfl_xor_sync(FULL, sq, 2, 32);
                sq += __shfl_xor_sync(FULL, sq, 4, 32);
                const float mean = sm * (1.f / H);
                const float var  = fmaf(-mean, mean, sq * (1.f / H));
                const float rstd = rsqrtf(var + LN_EPS);
                #pragma unroll
                for (int cp = 0; cp < 4; cp++) {
                    float px, py;
                    upk2(px, py, pre[s][cp]);
                    const float fx = tanh_fast(fmaf((px - mean) * rstd, lnw2[cp].x, lnb2[cp].x));
                    const float fy = tanh_fast(fmaf((py - mean) * rstd, lnw2[cp].y, lnb2[cp].y));
                    float hx = fmaf(DT, fx, fmaf(-dec2[cp].x, hv2[s][cp].x, hv2[s][cp].x));
                    float hy = fmaf(DT, fy, fmaf(-dec2[cp].y, hv2[s][cp].y, hv2[s][cp].y));
                    hv2[s][cp].x = fminf(10.f, fmaxf(-10.f, hx));
                    hv2[s][cp].y = fminf(10.f, fmaxf(-10.f, hy));
                }
            }
            // publish h (duplicated) to slab
            __syncwarp();
            #pragma unroll
            for (int cc = 0; cc < 8; cc++) {
                const int cp = cc >> 1;
                float v0, v1, v2, v3;
                if (cc & 1) { v0 = hv2[0][cp].y; v1 = hv2[1][cp].y; v2 = hv2[2][cp].y; v3 = hv2[3][cp].y; }
                else        { v0 = hv2[0][cp].x; v1 = hv2[1][cp].x; v2 = hv2[2][cp].x; v3 = hv2[3][cp].x; }
                const int idx2 = ((c0 + cc) * 4 + myslot) * 2;
                HsW[idx2]     = make_ulonglong2(dup2(v0), dup2(v1));
                HsW[idx2 + 1] = make_ulonglong2(dup2(v2), dup2(v3));
            }
            __syncwarp();
        }
    }

    // ================= Phase 2: x = h @ Wx0^T + bx0 =================
    __syncthreads();
    for (int i = tid; i < AA * AA; i += TPB) sWgt[i] = g_wx0t[i];
    if (tid < AA) s_vec[tid] = bx0[tid];
    __syncthreads();

    float2 xv[4][4];
    {
        const ulonglong2* sWu = reinterpret_cast<const ulonglong2*>(sWgt);
        uint64_t xp[4][4];
        #pragma unroll
        for (int cp = 0; cp < 4; cp++) {
            const uint64_t b2 = pk2(s_vec[c0 + 2 * cp], s_vec[c0 + 2 * cp + 1]);
            #pragma unroll
            for (int s = 0; s < 4; s++) xp[s][cp] = b2;
        }
        for (int q = 0; q < 8; q++) {
            const int sl = sg ^ (q & 3);
            #pragma unroll
            for (int r = 0; r < 8; r++) {
                const int i = q * 8 + r;
                const ulonglong2 ha = HsW[(i * 4 + sl) * 2];
                const ulonglong2 hb = HsW[(i * 4 + sl) * 2 + 1];
                const ulonglong2 wa = sWu[i * 16 + cg * 2];
                const ulonglong2 wb = sWu[i * 16 + cg * 2 + 1];
                ffma2(xp[0][0], ha.x, wa.x); ffma2(xp[0][1], ha.x, wa.y);
                ffma2(xp[0][2], ha.x, wb.x); ffma2(xp[0][3], ha.x, wb.y);
                ffma2(xp[1][0], ha.y, wa.x); ffma2(xp[1][1], ha.y, wa.y);
                ffma2(xp[1][2], ha.y, wb.x); ffma2(xp[1][3], ha.y, wb.y);
                ffma2(xp[2][0], hb.x, wa.x); ffma2(xp[2][1], hb.x, wa.y);
                ffma2(xp[2][2], hb.x, wb.x); ffma2(xp[2][3], hb.x, wb.y);
                ffma2(xp[3][0], hb.y, wa.x); ffma2(xp[3][1], hb.y, wa.y);
                ffma2(xp[3][2], hb.y, wb.x); ffma2(xp[3][3], hb.y, wb.y);
            }
        }
        #pragma unroll
        for (int s = 0; s < 4; s++)
            #pragma unroll
            for (int cp = 0; cp < 4; cp++)
                upk2(xv[s][cp].x, xv[s][cp].y, xp[s][cp]);
    }
    // publish x (duplicated)
    __syncwarp();
    #pragma unroll
    for (int cc = 0; cc < 8; cc++) {
        const int cp = cc >> 1;
        float v0, v1, v2, v3;
        if (cc & 1) { v0 = xv[0][cp].y; v1 = xv[1][cp].y; v2 = xv[2][cp].y; v3 = xv[3][cp].y; }
        else        { v0 = xv[0][cp].x; v1 = xv[1][cp].x; v2 = xv[2][cp].x; v3 = xv[3][cp].x; }
        const int idx2 = ((c0 + cc) * 4 + myslot) * 2;
        HsW[idx2]     = make_ulonglong2(dup2(v0), dup2(v1));
        HsW[idx2 + 1] = make_ulonglong2(dup2(v2), dup2(v3));
    }
    __syncwarp();

    // ================= Phase 3: ISTA iterations =================
    for (int k = 0; k < KK; k++) {
        __syncthreads();
        {
            const float4* wet4 = reinterpret_cast<const float4*>(g_wet + k * WIN * AA);
            const float4* wrt4 = reinterpret_cast<const float4*>(g_wrt + k * AA * AA);
            float4* d4 = reinterpret_cast<float4*>(sWgt);
            for (int i = tid; i < (WIN * AA) / 4; i += TPB) d4[i] = wet4[i];
            float4* e4 = reinterpret_cast<float4*>(sWgt + WIN * AA);
            for (int i = tid; i < (AA * AA) / 4; i += TPB) e4[i] = wrt4[i];
            if (tid < AA) {
                s_vec[tid] = be[k * AA + tid];
                s_lam[tid] = softplus_f(thr[k * AA + tid]);
            }
        }
        __syncthreads();

        const ulonglong2* sWeu = reinterpret_cast<const ulonglong2*>(sWgt);
        const ulonglong2* sWru = reinterpret_cast<const ulonglong2*>(sWgt + WIN * AA);

        uint64_t z[4][4];
        #pragma unroll
        for (int cp = 0; cp < 4; cp++) {
            const uint64_t b2 = pk2(s_vec[c0 + 2 * cp], s_vec[c0 + 2 * cp + 1]);
            #pragma unroll
            for (int s = 0; s < 4; s++) z[s][cp] = b2;
        }
        // z += y @ We_k^T  (y pre-duplicated in gmem)
        #pragma unroll 4
        for (int t = 0; t < WIN; t++) {
            const ulonglong2* ydu = reinterpret_cast<const ulonglong2*>(g_ytd + (size_t)t * BMAX + s0);
            const ulonglong2 ya = __ldg(&ydu[0]);
            const ulonglong2 yb = __ldg(&ydu[1]);
            const ulonglong2 wa = sWeu[t * 16 + cg * 2];
            const ulonglong2 wb = sWeu[t * 16 + cg * 2 + 1];
            ffma2(z[0][0], ya.x, wa.x); ffma2(z[0][1], ya.x, wa.y);
            ffma2(z[0][2], ya.x, wb.x); ffma2(z[0][3], ya.x, wb.y);
            ffma2(z[1][0], ya.y, wa.x); ffma2(z[1][1], ya.y, wa.y);
            ffma2(z[1][2], ya.y, wb.x); ffma2(z[1][3], ya.y, wb.y);
            ffma2(z[2][0], yb.x, wa.x); ffma2(z[2][1], yb.x, wa.y);
            ffma2(z[2][2], yb.x, wb.x); ffma2(z[2][3], yb.x, wb.y);
            ffma2(z[3][0], yb.y, wa.x); ffma2(z[3][1], yb.y, wa.y);
            ffma2(z[3][2], yb.y, wb.x); ffma2(z[3][3], yb.y, wb.y);
        }
        // z += x @ Wr_k^T
        for (int q = 0; q < 8; q++) {
            const int sl = sg ^ (q & 3);
            #pragma unroll
            for (int r = 0; r < 8; r++) {
                const int i = q * 8 + r;
                const ulonglong2 ha = HsW[(i * 4 + sl) * 2];
                const ulonglong2 hb = HsW[(i * 4 + sl) * 2 + 1];
                const ulonglong2 wa = sWru[i * 16 + cg * 2];
                const ulonglong2 wb = sWru[i * 16 + cg * 2 + 1];
                ffma2(z[0][0], ha.x, wa.x); ffma2(z[0][1], ha.x, wa.y);
                ffma2(z[0][2], ha.x, wb.x); ffma2(z[0][3], ha.x, wb.y);
                ffma2(z[1][0], ha.y, wa.x); ffma2(z[1][1], ha.y, wa.y);
                ffma2(z[1][2], ha.y, wb.x); ffma2(z[1][3], ha.y, wb.y);
                ffma2(z[2][0], hb.x, wa.x); ffma2(z[2][1], hb.x, wa.y);
                ffma2(z[2][2], hb.x, wb.x); ffma2(z[2][3], hb.x, wb.y);
                ffma2(z[3][0], hb.y, wa.x); ffma2(z[3][1], hb.y, wa.y);
                ffma2(z[3][2], hb.y, wb.x); ffma2(z[3][3], hb.y, wb.y);
            }
        }
        // soft threshold -> xv
        #pragma unroll
        for (int cp = 0; cp < 4; cp++) {
            const float2 lam2 = make_float2(s_lam[c0 + 2 * cp], s_lam[c0 + 2 * cp + 1]);
            #pragma unroll
            for (int s = 0; s < 4; s++) {
                float zx, zy;
                upk2(zx, zy, z[s][cp]);
                xv[s][cp].x = copysignf(fmaxf(fabsf(zx) - lam2.x, 0.f), zx);
                xv[s][cp].y = copysignf(fmaxf(fabsf(zy) - lam2.y, 0.f), zy);
            }
        }
        // publish x (duplicated)
        __syncwarp();
        #pragma unroll
        for (int cc = 0; cc < 8; cc++) {
            const int cp = cc >> 1;
            float v0, v1, v2, v3;
            if (cc & 1) { v0 = xv[0][cp].y; v1 = xv[1][cp].y; v2 = xv[2][cp].y; v3 = xv[3][cp].y; }
            else        { v0 = xv[0][cp].x; v1 = xv[1][cp].x; v2 = xv[2][cp].x; v3 = xv[3][cp].x; }
            const int idx2 = ((c0 + cc) * 4 + myslot) * 2;
            HsW[idx2]     = make_ulonglong2(dup2(v0), dup2(v1));
            HsW[idx2 + 1] = make_ulonglong2(dup2(v2), dup2(v3));
        }
        __syncwarp();
    }

    // ================= Phase 4: heads + outputs (weights straight from gmem) =================
    {
        float p[4][NAPP];
        #pragma unroll
        for (int n = 0; n < NAPP; n++) {
            float2 hw[4];
            #pragma unroll
            for (int cp = 0; cp < 4; cp++)
                hw[cp] = __ldg(reinterpret_cast<const float2*>(head_W + n * AA + c0 + 2 * cp));
            #pragma unroll
            for (int s = 0; s < 4; s++) {
                float acc = 0.f;
                #pragma unroll
                for (int cp = 0; cp < 4; cp++) {
                    acc = fmaf(xv[s][cp].x, hw[cp].x, acc);
                    acc = fmaf(xv[s][cp].y, hw[cp].y, acc);
                }
                acc += __shfl_xor_sync(FULL, acc, 1, 32);
                acc += __shfl_xor_sync(FULL, acc, 2, 32);
                acc += __shfl_xor_sync(FULL, acc, 4, 32);
                p[s][n] = acc;
            }
        }
        #pragma unroll
        for (int s = 0; s < 4; s++) {
            const int b = s0 + s;
            if (b < B) {
                if (cg == 0) {
                    float4 pw = make_float4(p[s][0] + __ldg(&head_b[0]), p[s][1] + __ldg(&head_b[1]),
                                            p[s][2] + __ldg(&head_b[2]), p[s][3] + __ldg(&head_b[3]));
                    *reinterpret_cast<float4*>(out_power + (long)b * NAPP) = pw;
                }
                float4* xo = reinterpret_cast<float4*>(out_x + (long)b * AA + c0);
                xo[0] = make_float4(xv[s][0].x, xv[s][0].y, xv[s][1].x, xv[s][1].y);
                xo[1] = make_float4(xv[s][2].x, xv[s][2].y, xv[s][3].x, xv[s][3].y);
            }
        }
    }
}

extern "C" void kernel_launch(void* const* d_in, const int* in_sizes, int n_in,
                              void* d_out, int out_size)
{
    const float* y         = (const float*)d_in[0];
    const float* w_in      = (const float*)d_in[1];
    const float* b_in      = (const float*)d_in[2];
    const float* tau_param = (const float*)d_in[3];
    const float* W_rec     = (const float*)d_in[4];
    const float* ln_w      = (const float*)d_in[5];
    const float* ln_b      = (const float*)d_in[6];
    const float* Wx0       = (const float*)d_in[7];
    const float* bx0       = (const float*)d_in[8];
    const float* We        = (const float*)d_in[9];
    const float* be        = (const float*)d_in[10];
    const float* Wr        = (const float*)d_in[11];
    const float* thr       = (const float*)d_in[12];
    const float* head_W    = (const float*)d_in[13];
    const float* head_b    = (const float*)d_in[14];

    const int B = in_sizes[0] / WIN;

    float* out       = (float*)d_out;
    float* out_power = out;
    float* out_x     = out + (size_t)B * NAPP;

    {
        const int nBB = (B + 31) / 32;
        const int nYBlocks = nBB * ((WIN + 31) / 32);
        const int wTotal = KK * WIN * AA + KK * AA * AA + AA * AA;
        const int nWBlocks = (wTotal + 255) / 256;
        prep_all_kernel<<<nYBlocks + nWBlocks, 256>>>(y, We, Wr, Wx0, B, nBB, nYBlocks);
    }

    cudaFuncSetAttribute(pinn_main_kernel,
                         cudaFuncAttributeMaxDynamicSharedMemorySize,
                         (int)DYN_BYTES);

    const int grid = (B + SPC - 1) / SPC;
    pinn_main_kernel<<<grid, TPB, DYN_BYTES>>>(
        w_in, b_in, tau_param, W_rec, ln_w, ln_b,
        bx0, be, thr, head_W, head_b,
        out_power, out_x, B);
}

// round 16
// speedup vs baseline: 1.1177x; 1.1177x over previous
#include <cuda_runtime.h>
#include <cstdint>

#define WIN    100
#define H      64
#define AA     64
#define KK     8
#define NAPP   4
#define DT     0.1f
#define LN_EPS 1e-5f
#define TPB    128
#define SPC    64
#define BMAX   32768

#define SWGT_FLOATS (WIN * AA)                  // 6400: max of W_rec(4096)/Wx0(4096)/We_t(6400)
#define SHS_FLOATS  (4 * H * 16)                // 4096 (per-warp h/x slabs, float4 slots)
#define DYN_BYTES   ((SWGT_FLOATS + SHS_FLOATS) * sizeof(float))   // 41,984 B -> 4 CTAs/SM fits

// gmem scratch
__device__ float g_yt[(size_t)WIN * BMAX];       // y transposed [t][b]
__device__ float g_wet[KK * WIN * AA];           // We transposed [k][t][a]
__device__ float g_wrt[KK * AA * AA];            // Wr transposed [k][i][a]
__device__ float g_wx0t[AA * AA];                // Wx0 transposed [i][a]

__device__ __forceinline__ float softplus_f(float v) {
    return (v > 20.f) ? v : log1pf(expf(v));
}
__device__ __forceinline__ float tanh_fast(float x) {
    float r; asm("tanh.approx.f32 %0, %1;" : "=f"(r) : "f"(x)); return r;
}
__device__ __forceinline__ uint64_t dup2(float a) {
    uint64_t r; asm("mov.b64 %0, {%1, %1};" : "=l"(r) : "f"(a)); return r;
}
__device__ __forceinline__ uint64_t pk2(float x, float y) {
    uint64_t r; asm("mov.b64 %0, {%1, %2};" : "=l"(r) : "f"(x), "f"(y)); return r;
}
__device__ __forceinline__ void upk2(float& x, float& y, uint64_t d) {
    asm("mov.b64 {%0, %1}, %2;" : "=f"(x), "=f"(y) : "l"(d));
}
__device__ __forceinline__ void ffma2(uint64_t& d, uint64_t a, uint64_t b) {
    asm("fma.rn.f32x2 %0, %1, %2, %0;" : "+l"(d) : "l"(a), "l"(b));
}
__device__ __forceinline__ void add2(uint64_t& d, uint64_t a) {
    asm("add.rn.f32x2 %0, %0, %1;" : "+l"(d) : "l"(a));
}

// ---------------- merged prep kernel ----------------
__global__ void prep_all_kernel(const float* __restrict__ y,
                                const float* __restrict__ We,
                                const float* __restrict__ Wr,
                                const float* __restrict__ Wx0,
                                int B, int nBB, int nYBlocks) {
    __shared__ float tile[32][33];
    const int tid = threadIdx.x;
    if ((int)blockIdx.x < nYBlocks) {
        const int bb = (blockIdx.x % nBB) * 32;
        const int tt = (blockIdx.x / nBB) * 32;
        const int tx = tid & 31, ty = tid >> 5;
        for (int r = ty; r < 32; r += 8) {
            const int b = bb + r, t = tt + tx;
            tile[r][tx] = (b < B && t < WIN) ? y[(long)b * WIN + t] : 0.f;
        }
        __syncthreads();
        for (int r = ty; r < 32; r += 8) {
            const int t = tt + r, b = bb + tx;
            if (t < WIN && b < B) g_yt[(size_t)t * BMAX + b] = tile[tx][r];
        }
        return;
    }
    const int idx = (blockIdx.x - nYBlocks) * blockDim.x + tid;
    if (idx < KK * WIN * AA) {
        const int k = idx / (WIN * AA);
        const int rem = idx - k * WIN * AA;
        const int t = rem >> 6, a = rem & 63;
        g_wet[idx] = We[k * AA * WIN + a * WIN + t];
        return;
    }
    const int i2 = idx - KK * WIN * AA;
    if (i2 >= 0 && i2 < KK * AA * AA) {
        const int k = i2 >> 12;
        const int rem = i2 & 4095;
        const int i = rem >> 6, a = rem & 63;
        g_wrt[i2] = Wr[k * AA * AA + a * AA + i];
        return;
    }
    const int i3 = i2 - KK * AA * AA;
    if (i3 >= 0 && i3 < AA * AA) {
        const int i = i3 >> 6, a = i3 & 63;
        g_wx0t[i3] = Wx0[a * AA + i];
    }
}

// ---------------- main kernel ----------------
__global__ __launch_bounds__(TPB, 4)     // 4 CTAs/SM: 16 warps/SM + single wave (512 <= 592)
void pinn_main_kernel(
    const float* __restrict__ w_in,
    const float* __restrict__ b_in,
    const float* __restrict__ tau_param,
    const float* __restrict__ W_rec,
    const float* __restrict__ ln_w,
    const float* __restrict__ ln_b,
    const float* __restrict__ bx0,
    const float* __restrict__ be,
    const float* __restrict__ thr,
    const float* __restrict__ head_W,
    const float* __restrict__ head_b,
    float* __restrict__ out_power,
    float* __restrict__ out_x,
    int B)
{
    extern __shared__ __align__(16) float smem[];
    float* sWgt = smem;                                   // phase-dependent weights
    float4* HsU = reinterpret_cast<float4*>(smem + SWGT_FLOATS);

    // small constants in static smem (keeps regs low)
    __shared__ uint64_t s_winp[H / 2], s_binp[H / 2];
    __shared__ float2 s_lnw2[H / 2], s_lnb2[H / 2], s_dec2[H / 2];
    __shared__ float s_vec[AA], s_lam[AA], s_head[NAPP * AA], s_headb[NAPP];

    const int tid  = threadIdx.x;
    const int warp = tid >> 5, lane = tid & 31;
    const int cg   = lane & 7;
    const int sg   = lane >> 3;
    const int c0   = cg * 8;
    const int cp0  = c0 / 2;
    const int s0   = blockIdx.x * SPC + warp * 16 + sg * 4;
    const unsigned FULL = 0xffffffffu;

    float4* HsW = HsU + warp * (H * 4);
    const int myslot = sg ^ (cg & 3);

    // ---- stage W_rec + params ----
    for (int i = tid; i < H * H; i += TPB) sWgt[i] = W_rec[i];
    if (tid < H / 2) {
        s_winp[tid] = pk2(w_in[2 * tid], w_in[2 * tid + 1]);
        s_binp[tid] = pk2(b_in[2 * tid], b_in[2 * tid + 1]);
        s_lnw2[tid] = make_float2(ln_w[2 * tid], ln_w[2 * tid + 1]);
        s_lnb2[tid] = make_float2(ln_b[2 * tid], ln_b[2 * tid + 1]);
        s_dec2[tid] = make_float2(DT / softplus_f(tau_param[2 * tid]),
                                  DT / softplus_f(tau_param[2 * tid + 1]));
    }
    for (int i = tid; i < NAPP * AA; i += TPB) s_head[i] = head_W[i];
    if (tid < NAPP) s_headb[tid] = head_b[tid];
    {
        const float4 z4 = make_float4(0.f, 0.f, 0.f, 0.f);
        #pragma unroll
        for (int cc = 0; cc < 8; cc++)
            HsW[(c0 + cc) * 4 + myslot] = z4;
    }
    __syncthreads();

    // ================= Phase 1: LNN recurrence =================
    float2 hv2[4][4];
    #pragma unroll
    for (int s = 0; s < 4; s++)
        #pragma unroll
        for (int cp = 0; cp < 4; cp++) hv2[s][cp] = make_float2(0.f, 0.f);

    {
        const ulonglong2* sWu = reinterpret_cast<const ulonglong2*>(sWgt);
        for (int t = 0; t < WIN; t++) {
            const float4 y4 = *reinterpret_cast<const float4*>(&g_yt[(size_t)t * BMAX + s0]);
            const uint64_t ys[4] = { dup2(y4.x), dup2(y4.y), dup2(y4.z), dup2(y4.w) };
            uint64_t pre[4][4];
            #pragma unroll
            for (int cp = 0; cp < 4; cp++) {
                const uint64_t wp = s_winp[cp0 + cp];
                const uint64_t bp = s_binp[cp0 + cp];
                #pragma unroll
                for (int s = 0; s < 4; s++) {
                    pre[s][cp] = bp;
                    ffma2(pre[s][cp], ys[s], wp);
                }
            }
            // pre += h @ W_rec : per i = 1 slab LDS.128 + 4 dup + 2 weight LDS.128 + 16 FFMA2
            for (int q = 0; q < 8; q++) {
                const int sl = sg ^ (q & 3);
                #pragma unroll
                for (int r = 0; r < 8; r++) {
                    const int i = q * 8 + r;
                    const float4 hv = HsW[i * 4 + sl];
                    const uint64_t h0 = dup2(hv.x), h1 = dup2(hv.y);
                    const uint64_t h2 = dup2(hv.z), h3 = dup2(hv.w);
                    const ulonglong2 wa = sWu[i * 16 + cg * 2];
                    const ulonglong2 wb = sWu[i * 16 + cg * 2 + 1];
                    ffma2(pre[0][0], h0, wa.x); ffma2(pre[0][1], h0, wa.y);
                    ffma2(pre[0][2], h0, wb.x); ffma2(pre[0][3], h0, wb.y);
                    ffma2(pre[1][0], h1, wa.x); ffma2(pre[1][1], h1, wa.y);
                    ffma2(pre[1][2], h1, wb.x); ffma2(pre[1][3], h1, wb.y);
                    ffma2(pre[2][0], h2, wa.x); ffma2(pre[2][1], h2, wa.y);
                    ffma2(pre[2][2], h2, wb.x); ffma2(pre[2][3], h2, wb.y);
                    ffma2(pre[3][0], h3, wa.x); ffma2(pre[3][1], h3, wa.y);
                    ffma2(pre[3][2], h3, wb.x); ffma2(pre[3][3], h3, wb.y);
                }
            }
            // LN + tanh + Euler (packed stats + octet shfl)
            #pragma unroll
            for (int s = 0; s < 4; s++) {
                uint64_t smp = 0ull, sqp = 0ull;
                #pragma unroll
                for (int cp = 0; cp < 4; cp++) {
                    add2(smp, pre[s][cp]);
                    ffma2(sqp, pre[s][cp], pre[s][cp]);
                }
                float smx, smy, sqx, sqy;
                upk2(smx, smy, smp);
                upk2(sqx, sqy, sqp);
                float sm = smx + smy, sq = sqx + sqy;
                sm += __shfl_xor_sync(FULL, sm, 1, 32);
                sm += __shfl_xor_sync(FULL, sm, 2, 32);
                sm += __shfl_xor_sync(FULL, sm, 4, 32);
                sq += __shfl_xor_sync(FULL, sq, 1, 32);
                sq += __shfl_xor_sync(FULL, sq, 2, 32);
                sq += __shfl_xor_sync(FULL, sq, 4, 32);
                const float mean = sm * (1.f / H);
                const float var  = fmaf(-mean, mean, sq * (1.f / H));
                const float rstd = rsqrtf(var + LN_EPS);
                #pragma unroll
                for (int cp = 0; cp < 4; cp++) {
                    const float2 lw = s_lnw2[cp0 + cp];
                    const float2 lb = s_lnb2[cp0 + cp];
                    const float2 dc = s_dec2[cp0 + cp];
                    float px, py;
                    upk2(px, py, pre[s][cp]);
                    const float fx = tanh_fast(fmaf((px - mean) * rstd, lw.x, lb.x));
                    const float fy = tanh_fast(fmaf((py - mean) * rstd, lw.y, lb.y));
                    float hx = fmaf(DT, fx, fmaf(-dc.x, hv2[s][cp].x, hv2[s][cp].x));
                    float hy = fmaf(DT, fy, fmaf(-dc.y, hv2[s][cp].y, hv2[s][cp].y));
                    hv2[s][cp].x = fminf(10.f, fmaxf(-10.f, hx));
                    hv2[s][cp].y = fminf(10.f, fmaxf(-10.f, hy));
                }
            }
            // publish h to per-warp slab
            __syncwarp();
            #pragma unroll
            for (int cc = 0; cc < 8; cc++) {
                const int cp = cc >> 1;
                float4 v;
                if (cc & 1) v = make_float4(hv2[0][cp].y, hv2[1][cp].y, hv2[2][cp].y, hv2[3][cp].y);
                else        v = make_float4(hv2[0][cp].x, hv2[1][cp].x, hv2[2][cp].x, hv2[3][cp].x);
                HsW[(c0 + cc) * 4 + myslot] = v;
            }
            __syncwarp();
        }
    }

    // ================= Phase 2: x = h @ Wx0^T + bx0 =================
    __syncthreads();
    for (int i = tid; i < AA * AA; i += TPB) sWgt[i] = g_wx0t[i];
    if (tid < AA) s_vec[tid] = bx0[tid];
    __syncthreads();

    float2 xv[4][4];
    {
        const ulonglong2* sWu = reinterpret_cast<const ulonglong2*>(sWgt);
        uint64_t xp[4][4];
        #pragma unroll
        for (int cp = 0; cp < 4; cp++) {
            const uint64_t b2 = pk2(s_vec[c0 + 2 * cp], s_vec[c0 + 2 * cp + 1]);
            #pragma unroll
            for (int s = 0; s < 4; s++) xp[s][cp] = b2;
        }
        for (int q = 0; q < 8; q++) {
            const int sl = sg ^ (q & 3);
            #pragma unroll
            for (int r = 0; r < 8; r++) {
                const int i = q * 8 + r;
                const float4 hv = HsW[i * 4 + sl];
                const uint64_t h0 = dup2(hv.x), h1 = dup2(hv.y);
                const uint64_t h2 = dup2(hv.z), h3 = dup2(hv.w);
                const ulonglong2 wa = sWu[i * 16 + cg * 2];
                const ulonglong2 wb = sWu[i * 16 + cg * 2 + 1];
                ffma2(xp[0][0], h0, wa.x); ffma2(xp[0][1], h0, wa.y);
                ffma2(xp[0][2], h0, wb.x); ffma2(xp[0][3], h0, wb.y);
                ffma2(xp[1][0], h1, wa.x); ffma2(xp[1][1], h1, wa.y);
                ffma2(xp[1][2], h1, wb.x); ffma2(xp[1][3], h1, wb.y);
                ffma2(xp[2][0], h2, wa.x); ffma2(xp[2][1], h2, wa.y);
                ffma2(xp[2][2], h2, wb.x); ffma2(xp[2][3], h2, wb.y);
                ffma2(xp[3][0], h3, wa.x); ffma2(xp[3][1], h3, wa.y);
                ffma2(xp[3][2], h3, wb.x); ffma2(xp[3][3], h3, wb.y);
            }
        }
        #pragma unroll
        for (int s = 0; s < 4; s++)
            #pragma unroll
            for (int cp = 0; cp < 4; cp++)
                upk2(xv[s][cp].x, xv[s][cp].y, xp[s][cp]);
    }
    // publish x into slab
    __syncwarp();
    #pragma unroll
    for (int cc = 0; cc < 8; cc++) {
        const int cp = cc >> 1;
        float4 v;
        if (cc & 1) v = make_float4(xv[0][cp].y, xv[1][cp].y, xv[2][cp].y, xv[3][cp].y);
        else        v = make_float4(xv[0][cp].x, xv[1][cp].x, xv[2][cp].x, xv[3][cp].x);
        HsW[(c0 + cc) * 4 + myslot] = v;
    }
    __syncwarp();

    // ================= Phase 3: ISTA iterations =================
    for (int k = 0; k < KK; k++) {
        __syncthreads();
        {
            // stage We_t only; Wr comes from gmem (L2-resident, shared by all CTAs)
            const float4* wet4 = reinterpret_cast<const float4*>(g_wet + k * WIN * AA);
            float4* d4 = reinterpret_cast<float4*>(sWgt);
            for (int i = tid; i < (WIN * AA) / 4; i += TPB) d4[i] = wet4[i];
            if (tid < AA) {
                s_vec[tid] = be[k * AA + tid];
                s_lam[tid] = softplus_f(thr[k * AA + tid]);
            }
        }
        __syncthreads();

        const ulonglong2* sWeu = reinterpret_cast<const ulonglong2*>(sWgt);
        const ulonglong2* gWru = reinterpret_cast<const ulonglong2*>(g_wrt + k * AA * AA);

        uint64_t z[4][4];
        #pragma unroll
        for (int cp = 0; cp < 4; cp++) {
            const uint64_t b2 = pk2(s_vec[c0 + 2 * cp], s_vec[c0 + 2 * cp + 1]);
            #pragma unroll
            for (int s = 0; s < 4; s++) z[s][cp] = b2;
        }
        // z += y @ We_k^T
        #pragma unroll 4
        for (int t = 0; t < WIN; t++) {
            const float4 y4 = *reinterpret_cast<const float4*>(&g_yt[(size_t)t * BMAX + s0]);
            const uint64_t q0 = dup2(y4.x), q1 = dup2(y4.y);
            const uint64_t q2 = dup2(y4.z), q3 = dup2(y4.w);
            const ulonglong2 wa = sWeu[t * 16 + cg * 2];
            const ulonglong2 wb = sWeu[t * 16 + cg * 2 + 1];
            ffma2(z[0][0], q0, wa.x); ffma2(z[0][1], q0, wa.y);
            ffma2(z[0][2], q0, wb.x); ffma2(z[0][3], q0, wb.y);
            ffma2(z[1][0], q1, wa.x); ffma2(z[1][1], q1, wa.y);
            ffma2(z[1][2], q1, wb.x); ffma2(z[1][3], q1, wb.y);
            ffma2(z[2][0], q2, wa.x); ffma2(z[2][1], q2, wa.y);
            ffma2(z[2][2], q2, wb.x); ffma2(z[2][3], q2, wb.y);
            ffma2(z[3][0], q3, wa.x); ffma2(z[3][1], q3, wa.y);
            ffma2(z[3][2], q3, wb.x); ffma2(z[3][3], q3, wb.y);
        }
        // z += x @ Wr_k^T  (slab x, gmem Wr)
        for (int q = 0; q < 8; q++) {
            const int sl = sg ^ (q & 3);
            #pragma unroll
            for (int r = 0; r < 8; r++) {
                const int i = q * 8 + r;
                const float4 hv = HsW[i * 4 + sl];
                const uint64_t h0 = dup2(hv.x), h1 = dup2(hv.y);
                const uint64_t h2 = dup2(hv.z), h3 = dup2(hv.w);
                const ulonglong2 wa = __ldg(&gWru[i * 16 + cg * 2]);
                const ulonglong2 wb = __ldg(&gWru[i * 16 + cg * 2 + 1]);
                ffma2(z[0][0], h0, wa.x); ffma2(z[0][1], h0, wa.y);
                ffma2(z[0][2], h0, wb.x); ffma2(z[0][3], h0, wb.y);
                ffma2(z[1][0], h1, wa.x); ffma2(z[1][1], h1, wa.y);
                ffma2(z[1][2], h1, wb.x); ffma2(z[1][3], h1, wb.y);
                ffma2(z[2][0], h2, wa.x); ffma2(z[2][1], h2, wa.y);
                ffma2(z[2][2], h2, wb.x); ffma2(z[2][3], h2, wb.y);
                ffma2(z[3][0], h3, wa.x); ffma2(z[3][1], h3, wa.y);
                ffma2(z[3][2], h3, wb.x); ffma2(z[3][3], h3, wb.y);
            }
        }
        // soft threshold -> xv
        #pragma unroll
        for (int cp = 0; cp < 4; cp++) {
            const float2 lam2 = make_float2(s_lam[c0 + 2 * cp], s_lam[c0 + 2 * cp + 1]);
            #pragma unroll
            for (int s = 0; s < 4; s++) {
                float zx, zy;
                upk2(zx, zy, z[s][cp]);
                xv[s][cp].x = copysignf(fmaxf(fabsf(zx) - lam2.x, 0.f), zx);
                xv[s][cp].y = copysignf(fmaxf(fabsf(zy) - lam2.y, 0.f), zy);
            }
        }
        // publish x
        __syncwarp();
        #pragma unroll
        for (int cc = 0; cc < 8; cc++) {
            const int cp = cc >> 1;
            float4 v;
            if (cc & 1) v = make_float4(xv[0][cp].y, xv[1][cp].y, xv[2][cp].y, xv[3][cp].y);
            else        v = make_float4(xv[0][cp].x, xv[1][cp].x, xv[2][cp].x, xv[3][cp].x);
            HsW[(c0 + cc) * 4 + myslot] = v;
        }
        __syncwarp();
    }

    // ================= Phase 4: heads + outputs =================
    {
        float p[4][NAPP];
        #pragma unroll
        for (int n = 0; n < NAPP; n++) {
            #pragma unroll
            for (int s = 0; s < 4; s++) {
                float acc = 0.f;
                #pragma unroll
                for (int cp = 0; cp < 4; cp++) {
                    acc = fmaf(xv[s][cp].x, s_head[n * AA + c0 + 2 * cp], acc);
                    acc = fmaf(xv[s][cp].y, s_head[n * AA + c0 + 2 * cp + 1], acc);
                }
                acc += __shfl_xor_sync(FULL, acc, 1, 32);
                acc += __shfl_xor_sync(FULL, acc, 2, 32);
                acc += __shfl_xor_sync(FULL, acc, 4, 32);
                p[s][n] = acc;
            }
        }
        #pragma unroll
        for (int s = 0; s < 4; s++) {
            const int b = s0 + s;
            if (b < B) {
                if (cg == 0) {
                    float4 pw = make_float4(p[s][0] + s_headb[0], p[s][1] + s_headb[1],
                                            p[s][2] + s_headb[2], p[s][3] + s_headb[3]);
                    *reinterpret_cast<float4*>(out_power + (long)b * NAPP) = pw;
                }
                float4* xo = reinterpret_cast<float4*>(out_x + (long)b * AA + c0);
                xo[0] = make_float4(xv[s][0].x, xv[s][0].y, xv[s][1].x, xv[s][1].y);
                xo[1] = make_float4(xv[s][2].x, xv[s][2].y, xv[s][3].x, xv[s][3].y);
            }
        }
    }
}

extern "C" void kernel_launch(void* const* d_in, const int* in_sizes, int n_in,
                              void* d_out, int out_size)
{
    const float* y         = (const float*)d_in[0];
    const float* w_in      = (const float*)d_in[1];
    const float* b_in      = (const float*)d_in[2];
    const float* tau_param = (const float*)d_in[3];
    const float* W_rec     = (const float*)d_in[4];
    const float* ln_w      = (const float*)d_in[5];
    const float* ln_b      = (const float*)d_in[6];
    const float* Wx0       = (const float*)d_in[7];
    const float* bx0       = (const float*)d_in[8];
    const float* We        = (const float*)d_in[9];
    const float* be        = (const float*)d_in[10];
    const float* Wr        = (const float*)d_in[11];
    const float* thr       = (const float*)d_in[12];
    const float* head_W    = (const float*)d_in[13];
    const float* head_b    = (const float*)d_in[14];

    const int B = in_sizes[0] / WIN;

    float* out       = (float*)d_out;
    float* out_power = out;
    float* out_x     = out + (size_t)B * NAPP;

    {
        const int nBB = (B + 31) / 32;
        const int nYBlocks = nBB * ((WIN + 31) / 32);
        const int wTotal = KK * WIN * AA + KK * AA * AA + AA * AA;
        const int nWBlocks = (wTotal + 255) / 256;
        prep_all_kernel<<<nYBlocks + nWBlocks, 256>>>(y, We, Wr, Wx0, B, nBB, nYBlocks);
    }

    cudaFuncSetAttribute(pinn_main_kernel,
                         cudaFuncAttributeMaxDynamicSharedMemorySize,
                         (int)DYN_BYTES);

    const int grid = (B + SPC - 1) / SPC;
    pinn_main_kernel<<<grid, TPB, DYN_BYTES>>>(
        w_in, b_in, tau_param, W_rec, ln_w, ln_b,
        bx0, be, thr, head_W, head_b,
        out_power, out_x, B);
}

// round 17
// speedup vs baseline: 1.1537x; 1.0322x over previous
#include <cuda_runtime.h>
#include <cstdint>

#define WIN    100
#define H      64
#define AA     64
#define KK     8
#define NAPP   4
#define DT     0.1f
#define LN_EPS 1e-5f
#define TPB    128
#define SPC    64
#define BMAX   32768

// gmem scratch
__device__ float g_yt[(size_t)WIN * BMAX];       // y transposed [t][b]
__device__ float g_wet[KK * WIN * AA];           // We transposed [k][t][a]
__device__ float g_wrt[KK * AA * AA];            // Wr transposed [k][i][a]
__device__ float g_wx0t[AA * AA];                // Wx0 transposed [i][a]

__device__ __forceinline__ float softplus_f(float v) {
    return (v > 20.f) ? v : log1pf(expf(v));
}
__device__ __forceinline__ float tanh_fast(float x) {
    float r; asm("tanh.approx.f32 %0, %1;" : "=f"(r) : "f"(x)); return r;
}
__device__ __forceinline__ uint64_t dup2(float a) {
    uint64_t r; asm("mov.b64 %0, {%1, %1};" : "=l"(r) : "f"(a)); return r;
}
__device__ __forceinline__ uint64_t pk2(float x, float y) {
    uint64_t r; asm("mov.b64 %0, {%1, %2};" : "=l"(r) : "f"(x), "f"(y)); return r;
}
__device__ __forceinline__ void upk2(float& x, float& y, uint64_t d) {
    asm("mov.b64 {%0, %1}, %2;" : "=f"(x), "=f"(y) : "l"(d));
}
__device__ __forceinline__ void ffma2(uint64_t& d, uint64_t a, uint64_t b) {
    asm("fma.rn.f32x2 %0, %1, %2, %0;" : "+l"(d) : "l"(a), "l"(b));
}
__device__ __forceinline__ void add2(uint64_t& d, uint64_t a) {
    asm("add.rn.f32x2 %0, %0, %1;" : "+l"(d) : "l"(a));
}
// 16B LDG through the coalescing/dedup path
__device__ __forceinline__ ulonglong2 ldg2(const ulonglong2* p) {
    return __ldg(p);
}

// ---------------- merged prep kernel ----------------
__global__ void prep_all_kernel(const float* __restrict__ y,
                                const float* __restrict__ We,
                                const float* __restrict__ Wr,
                                const float* __restrict__ Wx0,
                                int B, int nBB, int nYBlocks) {
    __shared__ float tile[32][33];
    const int tid = threadIdx.x;
    if ((int)blockIdx.x < nYBlocks) {
        const int bb = (blockIdx.x % nBB) * 32;
        const int tt = (blockIdx.x / nBB) * 32;
        const int tx = tid & 31, ty = tid >> 5;
        for (int r = ty; r < 32; r += 8) {
            const int b = bb + r, t = tt + tx;
            tile[r][tx] = (b < B && t < WIN) ? y[(long)b * WIN + t] : 0.f;
        }
        __syncthreads();
        for (int r = ty; r < 32; r += 8) {
            const int t = tt + r, b = bb + tx;
            if (t < WIN && b < B) g_yt[(size_t)t * BMAX + b] = tile[tx][r];
        }
        return;
    }
    const int idx = (blockIdx.x - nYBlocks) * blockDim.x + tid;
    if (idx < KK * WIN * AA) {
        const int k = idx / (WIN * AA);
        const int rem = idx - k * WIN * AA;
        const int t = rem >> 6, a = rem & 63;
        g_wet[idx] = We[k * AA * WIN + a * WIN + t];
        return;
    }
    const int i2 = idx - KK * WIN * AA;
    if (i2 >= 0 && i2 < KK * AA * AA) {
        const int k = i2 >> 12;
        const int rem = i2 & 4095;
        const int i = rem >> 6, a = rem & 63;
        g_wrt[i2] = Wr[k * AA * AA + a * AA + i];
        return;
    }
    const int i3 = i2 - KK * AA * AA;
    if (i3 >= 0 && i3 < AA * AA) {
        const int i = i3 >> 6, a = i3 & 63;
        g_wx0t[i3] = Wx0[a * AA + i];
    }
}

// ---------------- main kernel ----------------
// Weights come through the LDG/L1-cache path (warp-wide dedup); smem holds only
// the per-warp h/x slab + small constants. Occupancy is register-limited (~3 CTAs).
__global__ __launch_bounds__(TPB)
void pinn_main_kernel(
    const float* __restrict__ w_in,
    const float* __restrict__ b_in,
    const float* __restrict__ tau_param,
    const float* __restrict__ W_rec,       // [i][ch] — already the layout we need
    const float* __restrict__ ln_w,
    const float* __restrict__ ln_b,
    const float* __restrict__ bx0,
    const float* __restrict__ be,
    const float* __restrict__ thr,
    const float* __restrict__ head_W,
    const float* __restrict__ head_b,
    float* __restrict__ out_power,
    float* __restrict__ out_x,
    int B)
{
    __shared__ __align__(16) float4 HsAll[4][H * 4];   // per-warp slabs, 16 KB
    __shared__ uint64_t s_winp[H / 2], s_binp[H / 2];
    __shared__ float2 s_lnw2[H / 2], s_lnb2[H / 2], s_dec2[H / 2];
    __shared__ float s_vec[AA], s_lam[AA], s_head[NAPP * AA], s_headb[NAPP];

    const int tid  = threadIdx.x;
    const int warp = tid >> 5, lane = tid & 31;
    const int cg   = lane & 7;
    const int sg   = lane >> 3;
    const int c0   = cg * 8;
    const int cp0  = c0 / 2;
    const int s0   = blockIdx.x * SPC + warp * 16 + sg * 4;
    const unsigned FULL = 0xffffffffu;

    float4* HsW = HsAll[warp];
    const int myslot = sg ^ (cg & 3);

    // ---- stage small params ----
    if (tid < H / 2) {
        s_winp[tid] = pk2(w_in[2 * tid], w_in[2 * tid + 1]);
        s_binp[tid] = pk2(b_in[2 * tid], b_in[2 * tid + 1]);
        s_lnw2[tid] = make_float2(ln_w[2 * tid], ln_w[2 * tid + 1]);
        s_lnb2[tid] = make_float2(ln_b[2 * tid], ln_b[2 * tid + 1]);
        s_dec2[tid] = make_float2(DT / softplus_f(tau_param[2 * tid]),
                                  DT / softplus_f(tau_param[2 * tid + 1]));
    }
    for (int i = tid; i < NAPP * AA; i += TPB) s_head[i] = head_W[i];
    if (tid < NAPP) s_headb[tid] = head_b[tid];
    {
        const float4 z4 = make_float4(0.f, 0.f, 0.f, 0.f);
        #pragma unroll
        for (int cc = 0; cc < 8; cc++)
            HsW[(c0 + cc) * 4 + myslot] = z4;
    }
    __syncthreads();

    // ================= Phase 1: LNN recurrence =================
    float2 hv2[4][4];
    #pragma unroll
    for (int s = 0; s < 4; s++)
        #pragma unroll
        for (int cp = 0; cp < 4; cp++) hv2[s][cp] = make_float2(0.f, 0.f);

    {
        const ulonglong2* gWrec = reinterpret_cast<const ulonglong2*>(W_rec);
        for (int t = 0; t < WIN; t++) {
            const float4 y4 = *reinterpret_cast<const float4*>(&g_yt[(size_t)t * BMAX + s0]);
            const uint64_t ys[4] = { dup2(y4.x), dup2(y4.y), dup2(y4.z), dup2(y4.w) };
            uint64_t pre[4][4];
            #pragma unroll
            for (int cp = 0; cp < 4; cp++) {
                const uint64_t wp = s_winp[cp0 + cp];
                const uint64_t bp = s_binp[cp0 + cp];
                #pragma unroll
                for (int s = 0; s < 4; s++) {
                    pre[s][cp] = bp;
                    ffma2(pre[s][cp], ys[s], wp);
                }
            }
            // pre += h @ W_rec : slab LDS + weights via LDG (dedup'd, L1-hit)
            for (int q = 0; q < 8; q++) {
                const int sl = sg ^ (q & 3);
                #pragma unroll
                for (int r = 0; r < 8; r++) {
                    const int i = q * 8 + r;
                    const float4 hv = HsW[i * 4 + sl];
                    const uint64_t h0 = dup2(hv.x), h1 = dup2(hv.y);
                    const uint64_t h2 = dup2(hv.z), h3 = dup2(hv.w);
                    const ulonglong2 wa = ldg2(&gWrec[i * 16 + cg * 2]);
                    const ulonglong2 wb = ldg2(&gWrec[i * 16 + cg * 2 + 1]);
                    ffma2(pre[0][0], h0, wa.x); ffma2(pre[0][1], h0, wa.y);
                    ffma2(pre[0][2], h0, wb.x); ffma2(pre[0][3], h0, wb.y);
                    ffma2(pre[1][0], h1, wa.x); ffma2(pre[1][1], h1, wa.y);
                    ffma2(pre[1][2], h1, wb.x); ffma2(pre[1][3], h1, wb.y);
                    ffma2(pre[2][0], h2, wa.x); ffma2(pre[2][1], h2, wa.y);
                    ffma2(pre[2][2], h2, wb.x); ffma2(pre[2][3], h2, wb.y);
                    ffma2(pre[3][0], h3, wa.x); ffma2(pre[3][1], h3, wa.y);
                    ffma2(pre[3][2], h3, wb.x); ffma2(pre[3][3], h3, wb.y);
                }
            }
            // LN + tanh + Euler (packed stats + octet shfl)
            #pragma unroll
            for (int s = 0; s < 4; s++) {
                uint64_t smp = 0ull, sqp = 0ull;
                #pragma unroll
                for (int cp = 0; cp < 4; cp++) {
                    add2(smp, pre[s][cp]);
                    ffma2(sqp, pre[s][cp], pre[s][cp]);
                }
                float smx, smy, sqx, sqy;
                upk2(smx, smy, smp);
                upk2(sqx, sqy, sqp);
                float sm = smx + smy, sq = sqx + sqy;
                sm += __shfl_xor_sync(FULL, sm, 1, 32);
                sm += __shfl_xor_sync(FULL, sm, 2, 32);
                sm += __shfl_xor_sync(FULL, sm, 4, 32);
                sq += __shfl_xor_sync(FULL, sq, 1, 32);
                sq += __shfl_xor_sync(FULL, sq, 2, 32);
                sq += __shfl_xor_sync(FULL, sq, 4, 32);
                const float mean = sm * (1.f / H);
                const float var  = fmaf(-mean, mean, sq * (1.f / H));
                const float rstd = rsqrtf(var + LN_EPS);
                #pragma unroll
                for (int cp = 0; cp < 4; cp++) {
                    const float2 lw = s_lnw2[cp0 + cp];
                    const float2 lb = s_lnb2[cp0 + cp];
                    const float2 dc = s_dec2[cp0 + cp];
                    float px, py;
                    upk2(px, py, pre[s][cp]);
                    const float fx = tanh_fast(fmaf((px - mean) * rstd, lw.x, lb.x));
                    const float fy = tanh_fast(fmaf((py - mean) * rstd, lw.y, lb.y));
                    float hx = fmaf(DT, fx, fmaf(-dc.x, hv2[s][cp].x, hv2[s][cp].x));
                    float hy = fmaf(DT, fy, fmaf(-dc.y, hv2[s][cp].y, hv2[s][cp].y));
                    hv2[s][cp].x = fminf(10.f, fmaxf(-10.f, hx));
                    hv2[s][cp].y = fminf(10.f, fmaxf(-10.f, hy));
                }
            }
            // publish h to per-warp slab
            __syncwarp();
            #pragma unroll
            for (int cc = 0; cc < 8; cc++) {
                const int cp = cc >> 1;
                float4 v;
                if (cc & 1) v = make_float4(hv2[0][cp].y, hv2[1][cp].y, hv2[2][cp].y, hv2[3][cp].y);
                else        v = make_float4(hv2[0][cp].x, hv2[1][cp].x, hv2[2][cp].x, hv2[3][cp].x);
                HsW[(c0 + cc) * 4 + myslot] = v;
            }
            __syncwarp();
        }
    }

    // ================= Phase 2: x = h @ Wx0^T + bx0 =================
    if (tid < AA) s_vec[tid] = bx0[tid];
    __syncthreads();

    float2 xv[4][4];
    {
        const ulonglong2* gWx = reinterpret_cast<const ulonglong2*>(g_wx0t);
        uint64_t xp[4][4];
        #pragma unroll
        for (int cp = 0; cp < 4; cp++) {
            const uint64_t b2 = pk2(s_vec[c0 + 2 * cp], s_vec[c0 + 2 * cp + 1]);
            #pragma unroll
            for (int s = 0; s < 4; s++) xp[s][cp] = b2;
        }
        for (int q = 0; q < 8; q++) {
            const int sl = sg ^ (q & 3);
            #pragma unroll
            for (int r = 0; r < 8; r++) {
                const int i = q * 8 + r;
                const float4 hv = HsW[i * 4 + sl];
                const uint64_t h0 = dup2(hv.x), h1 = dup2(hv.y);
                const uint64_t h2 = dup2(hv.z), h3 = dup2(hv.w);
                const ulonglong2 wa = ldg2(&gWx[i * 16 + cg * 2]);
                const ulonglong2 wb = ldg2(&gWx[i * 16 + cg * 2 + 1]);
                ffma2(xp[0][0], h0, wa.x); ffma2(xp[0][1], h0, wa.y);
                ffma2(xp[0][2], h0, wb.x); ffma2(xp[0][3], h0, wb.y);
                ffma2(xp[1][0], h1, wa.x); ffma2(xp[1][1], h1, wa.y);
                ffma2(xp[1][2], h1, wb.x); ffma2(xp[1][3], h1, wb.y);
                ffma2(xp[2][0], h2, wa.x); ffma2(xp[2][1], h2, wa.y);
                ffma2(xp[2][2], h2, wb.x); ffma2(xp[2][3], h2, wb.y);
                ffma2(xp[3][0], h3, wa.x); ffma2(xp[3][1], h3, wa.y);
                ffma2(xp[3][2], h3, wb.x); ffma2(xp[3][3], h3, wb.y);
            }
        }
        #pragma unroll
        for (int s = 0; s < 4; s++)
            #pragma unroll
            for (int cp = 0; cp < 4; cp++)
                upk2(xv[s][cp].x, xv[s][cp].y, xp[s][cp]);
    }
    // publish x into slab
    __syncwarp();
    #pragma unroll
    for (int cc = 0; cc < 8; cc++) {
        const int cp = cc >> 1;
        float4 v;
        if (cc & 1) v = make_float4(xv[0][cp].y, xv[1][cp].y, xv[2][cp].y, xv[3][cp].y);
        else        v = make_float4(xv[0][cp].x, xv[1][cp].x, xv[2][cp].x, xv[3][cp].x);
        HsW[(c0 + cc) * 4 + myslot] = v;
    }
    __syncwarp();

    // ================= Phase 3: ISTA iterations =================
    for (int k = 0; k < KK; k++) {
        __syncthreads();
        if (tid < AA) {
            s_vec[tid] = be[k * AA + tid];
            s_lam[tid] = softplus_f(thr[k * AA + tid]);
        }
        __syncthreads();

        const ulonglong2* gWe = reinterpret_cast<const ulonglong2*>(g_wet + k * WIN * AA);
        const ulonglong2* gWr = reinterpret_cast<const ulonglong2*>(g_wrt + k * AA * AA);

        uint64_t z[4][4];
        #pragma unroll
        for (int cp = 0; cp < 4; cp++) {
            const uint64_t b2 = pk2(s_vec[c0 + 2 * cp], s_vec[c0 + 2 * cp + 1]);
            #pragma unroll
            for (int s = 0; s < 4; s++) z[s][cp] = b2;
        }
        // z += y @ We_k^T
        #pragma unroll 4
        for (int t = 0; t < WIN; t++) {
            const float4 y4 = *reinterpret_cast<const float4*>(&g_yt[(size_t)t * BMAX + s0]);
            const uint64_t q0 = dup2(y4.x), q1 = dup2(y4.y);
            const uint64_t q2 = dup2(y4.z), q3 = dup2(y4.w);
            const ulonglong2 wa = ldg2(&gWe[t * 16 + cg * 2]);
            const ulonglong2 wb = ldg2(&gWe[t * 16 + cg * 2 + 1]);
            ffma2(z[0][0], q0, wa.x); ffma2(z[0][1], q0, wa.y);
            ffma2(z[0][2], q0, wb.x); ffma2(z[0][3], q0, wb.y);
            ffma2(z[1][0], q1, wa.x); ffma2(z[1][1], q1, wa.y);
            ffma2(z[1][2], q1, wb.x); ffma2(z[1][3], q1, wb.y);
            ffma2(z[2][0], q2, wa.x); ffma2(z[2][1], q2, wa.y);
            ffma2(z[2][2], q2, wb.x); ffma2(z[2][3], q2, wb.y);
            ffma2(z[3][0], q3, wa.x); ffma2(z[3][1], q3, wa.y);
            ffma2(z[3][2], q3, wb.x); ffma2(z[3][3], q3, wb.y);
        }
        // z += x @ Wr_k^T  (slab x, LDG Wr)
        for (int q = 0; q < 8; q++) {
            const int sl = sg ^ (q & 3);
            #pragma unroll
            for (int r = 0; r < 8; r++) {
                const int i = q * 8 + r;
                const float4 hv = HsW[i * 4 + sl];
                const uint64_t h0 = dup2(hv.x), h1 = dup2(hv.y);
                const uint64_t h2 = dup2(hv.z), h3 = dup2(hv.w);
                const ulonglong2 wa = ldg2(&gWr[i * 16 + cg * 2]);
                const ulonglong2 wb = ldg2(&gWr[i * 16 + cg * 2 + 1]);
                ffma2(z[0][0], h0, wa.x); ffma2(z[0][1], h0, wa.y);
                ffma2(z[0][2], h0, wb.x); ffma2(z[0][3], h0, wb.y);
                ffma2(z[1][0], h1, wa.x); ffma2(z[1][1], h1, wa.y);
                ffma2(z[1][2], h1, wb.x); ffma2(z[1][3], h1, wb.y);
                ffma2(z[2][0], h2, wa.x); ffma2(z[2][1], h2, wa.y);
                ffma2(z[2][2], h2, wb.x); ffma2(z[2][3], h2, wb.y);
                ffma2(z[3][0], h3, wa.x); ffma2(z[3][1], h3, wa.y);
                ffma2(z[3][2], h3, wb.x); ffma2(z[3][3], h3, wb.y);
            }
        }
        // soft threshold -> xv
        #pragma unroll
        for (int cp = 0; cp < 4; cp++) {
            const float2 lam2 = make_float2(s_lam[c0 + 2 * cp], s_lam[c0 + 2 * cp + 1]);
            #pragma unroll
            for (int s = 0; s < 4; s++) {
                float zx, zy;
                upk2(zx, zy, z[s][cp]);
                xv[s][cp].x = copysignf(fmaxf(fabsf(zx) - lam2.x, 0.f), zx);
                xv[s][cp].y = copysignf(fmaxf(fabsf(zy) - lam2.y, 0.f), zy);
            }
        }
        // publish x
        __syncwarp();
        #pragma unroll
        for (int cc = 0; cc < 8; cc++) {
            const int cp = cc >> 1;
            float4 v;
            if (cc & 1) v = make_float4(xv[0][cp].y, xv[1][cp].y, xv[2][cp].y, xv[3][cp].y);
            else        v = make_float4(xv[0][cp].x, xv[1][cp].x, xv[2][cp].x, xv[3][cp].x);
            HsW[(c0 + cc) * 4 + myslot] = v;
        }
        __syncwarp();
    }

    // ================= Phase 4: heads + outputs =================
    {
        float p[4][NAPP];
        #pragma unroll
        for (int n = 0; n < NAPP; n++) {
            #pragma unroll
            for (int s = 0; s < 4; s++) {
                float acc = 0.f;
                #pragma unroll
                for (int cp = 0; cp < 4; cp++) {
                    acc = fmaf(xv[s][cp].x, s_head[n * AA + c0 + 2 * cp], acc);
                    acc = fmaf(xv[s][cp].y, s_head[n * AA + c0 + 2 * cp + 1], acc);
                }
                acc += __shfl_xor_sync(FULL, acc, 1, 32);
                acc += __shfl_xor_sync(FULL, acc, 2, 32);
                acc += __shfl_xor_sync(FULL, acc, 4, 32);
                p[s][n] = acc;
            }
        }
        #pragma unroll
        for (int s = 0; s < 4; s++) {
            const int b = s0 + s;
            if (b < B) {
                if (cg == 0) {
                    float4 pw = make_float4(p[s][0] + s_headb[0], p[s][1] + s_headb[1],
                                            p[s][2] + s_headb[2], p[s][3] + s_headb[3]);
                    *reinterpret_cast<float4*>(out_power + (long)b * NAPP) = pw;
                }
                float4* xo = reinterpret_cast<float4*>(out_x + (long)b * AA + c0);
                xo[0] = make_float4(xv[s][0].x, xv[s][0].y, xv[s][1].x, xv[s][1].y);
                xo[1] = make_float4(xv[s][2].x, xv[s][2].y, xv[s][3].x, xv[s][3].y);
            }
        }
    }
}

extern "C" void kernel_launch(void* const* d_in, const int* in_sizes, int n_in,
                              void* d_out, int out_size)
{
    const float* y         = (const float*)d_in[0];
    const float* w_in      = (const float*)d_in[1];
    const float* b_in      = (const float*)d_in[2];
    const float* tau_param = (const float*)d_in[3];
    const float* W_rec     = (const float*)d_in[4];
    const float* ln_w      = (const float*)d_in[5];
    const float* ln_b      = (const float*)d_in[6];
    const float* Wx0       = (const float*)d_in[7];
    const float* bx0       = (const float*)d_in[8];
    const float* We        = (const float*)d_in[9];
    const float* be        = (const float*)d_in[10];
    const float* Wr        = (const float*)d_in[11];
    const float* thr       = (const float*)d_in[12];
    const float* head_W    = (const float*)d_in[13];
    const float* head_b    = (const float*)d_in[14];

    const int B = in_sizes[0] / WIN;

    float* out       = (float*)d_out;
    float* out_power = out;
    float* out_x     = out + (size_t)B * NAPP;

    {
        const int nBB = (B + 31) / 32;
        const int nYBlocks = nBB * ((WIN + 31) / 32);
        const int wTotal = KK * WIN * AA + KK * AA * AA + AA * AA;
        const int nWBlocks = (wTotal + 255) / 256;
        prep_all_kernel<<<nYBlocks + nWBlocks, 256>>>(y, We, Wr, Wx0, B, nBB, nYBlocks);
    }

    const int grid = (B + SPC - 1) / SPC;
    pinn_main_kernel<<<grid, TPB>>>(
        w_in, b_in, tau_param, W_rec, ln_w, ln_b,
        bx0, be, thr, head_W, head_b,
        out_power, out_x, B);
}